// round 5
// baseline (speedup 1.0000x reference)
#include <cuda_runtime.h>
#include <math.h>

// Problem constants: B=1, N=256, Q=K=256, C=128, H=4, C_HID=32
#define NROW   65536
#define CDIM   128
#define NSEQ   256
#define NHEAD  4
#define CHID   32

// Scratch (allocation-free rule: __device__ globals)
__device__ float g_qbuf[(size_t)NROW * CDIM];
__device__ float g_kbuf[(size_t)NROW * CDIM];
__device__ float g_vbuf[(size_t)NROW * CDIM];
__device__ float g_gbuf[(size_t)NROW * CDIM];
__device__ float g_obuf[(size_t)NROW * CDIM];

// ---------------------------------------------------------------------------
// Packed f32x2 helpers (Blackwell dual-fp32 pipe)
// ---------------------------------------------------------------------------
typedef unsigned long long ull;

__device__ __forceinline__ ull pk2(float lo, float hi) {
    ull r;
    asm("mov.b64 %0, {%1, %2};" : "=l"(r) : "f"(lo), "f"(hi));
    return r;
}
__device__ __forceinline__ void upk2(ull v, float& lo, float& hi) {
    asm("mov.b64 {%0, %1}, %2;" : "=f"(lo), "=f"(hi) : "l"(v));
}
__device__ __forceinline__ ull ffma2(ull a, ull b, ull c) {
    ull d;
    asm("fma.rn.f32x2 %0, %1, %2, %3;" : "=l"(d) : "l"(a), "l"(b), "l"(c));
    return d;
}
__device__ __forceinline__ ull fmul2(ull a, ull b) {
    ull d;
    asm("mul.rn.f32x2 %0, %1, %2;" : "=l"(d) : "l"(a), "l"(b));
    return d;
}

union F4U2 {
    float4 f4;
    ull    u2[2];
};

// ---------------------------------------------------------------------------
// GEMM: Y[M,128] = epilogue( X[M,128] @ W[128,128] ), f32x2 mainloop.
// BM=128, BN=128, BK=16. 256 threads: tx=col group of 4 (2 pairs),
// ty=row group of 16. Per-thread tile 16x4.
// X stored as duplicated pairs, row-major, padded stride 18 ull -> one
// LDS.128 (warp-uniform, 1 wf) yields dup-pairs for k and k+1.
// Per 2k per warp: 8 wf (W) + 16 wf (X) = 24 wf vs 64 FFMA2 -> FMA-bound.
// ---------------------------------------------------------------------------
#define XSTR 18   // padded row stride in ull (144B, 16B-aligned, 2-way max STS)

__global__ void __launch_bounds__(256) gemm128_kernel(
    const float* __restrict__ X, const float* __restrict__ W,
    float* __restrict__ Y, int op, float alpha)
{
    __shared__ float sW[16 * 128];                    // 8KB
    __shared__ __align__(16) ull sXd[128 * XSTR];     // 18KB

    const int tid = threadIdx.x;
    const int m0  = blockIdx.x * 128;
    const int tx  = tid & 31;
    const int ty  = tid >> 5;

    ull acc[16][2];
#pragma unroll
    for (int r = 0; r < 16; r++) { acc[r][0] = 0ull; acc[r][1] = 0ull; }

    for (int k0 = 0; k0 < 128; k0 += 16) {
        // W tile: 16 rows x 128 cols = 512 float4
        {
            const float4* W4 = (const float4*)(W + (size_t)k0 * 128);
            float4* sW4 = (float4*)sW;
            sW4[tid]       = W4[tid];
            sW4[tid + 256] = W4[tid + 256];
        }
        // X tile: 128 rows x 16 k = 512 float4, expanded to dup-pairs
        {
#pragma unroll
            for (int i = 0; i < 2; i++) {
                int idx = tid + 256 * i;
                int row = idx >> 2, g = idx & 3;      // g: group of 4 k
                float4 x = *(const float4*)(X + ((size_t)(m0 + row)) * 128 + k0 + g * 4);
                ull* dst = &sXd[row * XSTR + g * 4];
                dst[0] = pk2(x.x, x.x);
                dst[1] = pk2(x.y, x.y);
                dst[2] = pk2(x.z, x.z);
                dst[3] = pk2(x.w, x.w);
            }
        }
        __syncthreads();

        const ull* xbase = &sXd[(ty * 16) * XSTR];
#pragma unroll
        for (int k = 0; k < 16; k += 2) {
            F4U2 wa, wb;
            wa.f4 = *(const float4*)&sW[k * 128 + tx * 4];
            wb.f4 = *(const float4*)&sW[(k + 1) * 128 + tx * 4];
#pragma unroll
            for (int r = 0; r < 16; r++) {
                F4U2 xp;                              // dup pairs for k, k+1
                xp.f4 = *(const float4*)&xbase[r * XSTR + k];
                acc[r][0] = ffma2(xp.u2[0], wa.u2[0], acc[r][0]);
                acc[r][1] = ffma2(xp.u2[0], wa.u2[1], acc[r][1]);
                acc[r][0] = ffma2(xp.u2[1], wb.u2[0], acc[r][0]);
                acc[r][1] = ffma2(xp.u2[1], wb.u2[1], acc[r][1]);
            }
        }
        __syncthreads();
    }

#pragma unroll
    for (int r = 0; r < 16; r++) {
        float4 o;
        upk2(acc[r][0], o.x, o.y);
        upk2(acc[r][1], o.z, o.w);
        if (op == 1) {
            o.x *= alpha; o.y *= alpha; o.z *= alpha; o.w *= alpha;
        } else if (op == 2) {
            o.x = 1.f / (1.f + __expf(-o.x));
            o.y = 1.f / (1.f + __expf(-o.y));
            o.z = 1.f / (1.f + __expf(-o.z));
            o.w = 1.f / (1.f + __expf(-o.w));
        }
        *(float4*)(Y + ((size_t)(m0 + ty * 16 + r)) * 128 + tx * 4) = o;
    }
}

// ---------------------------------------------------------------------------
// Attention: one CTA per (n, h), 128 threads, TWO q rows per thread
// (rows tid and tid+128). K/V broadcast wavefronts now feed 2x the FFMA2
// -> FMA-bound. Chunked online softmax (chunk=8) per row.
// ---------------------------------------------------------------------------
__global__ void __launch_bounds__(128) attn_kernel(
    const float* __restrict__ qb, const float* __restrict__ kb,
    const float* __restrict__ vb, const float* __restrict__ gb,
    const float* __restrict__ tri, const float* __restrict__ mb,
    float* __restrict__ ob)
{
    __shared__ float ks[128 * 32];
    __shared__ float vs[128 * 32];
    __shared__ float mbs[256];

    const int n   = blockIdx.x;
    const int h   = blockIdx.y;
    const int tid = threadIdx.x;
    const int r0  = tid;
    const int r1  = tid + 128;

    mbs[tid]       = mb[(size_t)n * 256 + tid];
    mbs[tid + 128] = mb[(size_t)n * 256 + tid + 128];

    const size_t qb0 = ((size_t)(n * 256 + r0)) * 128 + h * 32;
    const size_t qb1 = ((size_t)(n * 256 + r1)) * 128 + h * 32;
    ull qa[16], qc[16];
#pragma unroll
    for (int c = 0; c < 8; c++) {
        F4U2 t0; t0.f4 = *(const float4*)&qb[qb0 + c * 4];
        qa[2 * c] = t0.u2[0]; qa[2 * c + 1] = t0.u2[1];
        F4U2 t1; t1.f4 = *(const float4*)&qb[qb1 + c * 4];
        qc[2 * c] = t1.u2[0]; qc[2 * c + 1] = t1.u2[1];
    }
    const float* trow0 = tri + ((size_t)(h * 256 + r0)) * 256;
    const float* trow1 = tri + ((size_t)(h * 256 + r1)) * 256;

    float m0 = -INFINITY, l0 = 0.f, m1 = -INFINITY, l1 = 0.f;
    ull acc0[16], acc1[16];
#pragma unroll
    for (int c = 0; c < 16; c++) { acc0[c] = 0ull; acc1[c] = 0ull; }

    for (int jt = 0; jt < 256; jt += 128) {
        __syncthreads();
        {   // cooperative tile load: 128 rows x 8 float4 of head h
            const float4* kb4 = (const float4*)(kb + ((size_t)(n * 256 + jt)) * 128 + h * 32);
            const float4* vb4 = (const float4*)(vb + ((size_t)(n * 256 + jt)) * 128 + h * 32);
            float4* ks4 = (float4*)ks;
            float4* vs4 = (float4*)vs;
#pragma unroll
            for (int i = 0; i < 8; i++) {
                int idx = tid + 128 * i;               // 1024 float4 slots
                int row = idx >> 3, c4 = idx & 7;
                ks4[idx] = kb4[row * 32 + c4];
                vs4[idx] = vb4[row * 32 + c4];
            }
        }
        __syncthreads();

        for (int jc = 0; jc < 128; jc += 8) {
            float s0[8], s1[8];
            float4 ta0 = *(const float4*)&trow0[jt + jc];
            float4 ta1 = *(const float4*)&trow0[jt + jc + 4];
            float4 tc0 = *(const float4*)&trow1[jt + jc];
            float4 tc1 = *(const float4*)&trow1[jt + jc + 4];
            float tA[8] = {ta0.x, ta0.y, ta0.z, ta0.w, ta1.x, ta1.y, ta1.z, ta1.w};
            float tC[8] = {tc0.x, tc0.y, tc0.z, tc0.w, tc1.x, tc1.y, tc1.z, tc1.w};
#pragma unroll
            for (int u = 0; u < 8; u++) {
                const float4* kr = (const float4*)&ks[(jc + u) * 32];
                ull sa = 0ull, sb = 0ull;
#pragma unroll
                for (int c = 0; c < 8; c++) {
                    F4U2 kk; kk.f4 = kr[c];
                    sa = ffma2(qa[2 * c],     kk.u2[0], sa);
                    sa = ffma2(qa[2 * c + 1], kk.u2[1], sa);
                    sb = ffma2(qc[2 * c],     kk.u2[0], sb);
                    sb = ffma2(qc[2 * c + 1], kk.u2[1], sb);
                }
                float alo, ahi, blo, bhi;
                upk2(sa, alo, ahi);
                upk2(sb, blo, bhi);
                float mbv = mbs[jt + jc + u];
                s0[u] = alo + ahi + tA[u] + mbv;
                s1[u] = blo + bhi + tC[u] + mbv;
            }
            // chunk max + single rescale, per row
            float c0 = s0[0], c1 = s1[0];
#pragma unroll
            for (int u = 1; u < 8; u++) { c0 = fmaxf(c0, s0[u]); c1 = fmaxf(c1, s1[u]); }
            float mn0 = fmaxf(m0, c0), mn1 = fmaxf(m1, c1);
            float cr0 = __expf(m0 - mn0), cr1 = __expf(m1 - mn1);
            m0 = mn0; m1 = mn1;
            l0 *= cr0; l1 *= cr1;
            ull cp0 = pk2(cr0, cr0), cp1 = pk2(cr1, cr1);
#pragma unroll
            for (int c = 0; c < 16; c++) {
                acc0[c] = fmul2(acc0[c], cp0);
                acc1[c] = fmul2(acc1[c], cp1);
            }
#pragma unroll
            for (int u = 0; u < 8; u++) {
                float p0 = __expf(s0[u] - m0);
                float p1 = __expf(s1[u] - m1);
                l0 += p0; l1 += p1;
                ull pp0 = pk2(p0, p0), pp1 = pk2(p1, p1);
                const float4* vr = (const float4*)&vs[(jc + u) * 32];
#pragma unroll
                for (int c = 0; c < 8; c++) {
                    F4U2 vv; vv.f4 = vr[c];
                    acc0[2 * c]     = ffma2(pp0, vv.u2[0], acc0[2 * c]);
                    acc0[2 * c + 1] = ffma2(pp0, vv.u2[1], acc0[2 * c + 1]);
                    acc1[2 * c]     = ffma2(pp1, vv.u2[0], acc1[2 * c]);
                    acc1[2 * c + 1] = ffma2(pp1, vv.u2[1], acc1[2 * c + 1]);
                }
            }
        }
    }

    const float inv0 = 1.f / l0;
    const float inv1 = 1.f / l1;
#pragma unroll
    for (int c = 0; c < 8; c++) {
        float4 g0 = *(const float4*)&gb[qb0 + c * 4];
        float4 g1 = *(const float4*)&gb[qb1 + c * 4];
        float a0, a1, a2, a3;
        upk2(acc0[2 * c],     a0, a1);
        upk2(acc0[2 * c + 1], a2, a3);
        float4 o0;
        o0.x = a0 * inv0 * g0.x; o0.y = a1 * inv0 * g0.y;
        o0.z = a2 * inv0 * g0.z; o0.w = a3 * inv0 * g0.w;
        *(float4*)&ob[qb0 + c * 4] = o0;
        upk2(acc1[2 * c],     a0, a1);
        upk2(acc1[2 * c + 1], a2, a3);
        float4 o1;
        o1.x = a0 * inv1 * g1.x; o1.y = a1 * inv1 * g1.y;
        o1.z = a2 * inv1 * g1.z; o1.w = a3 * inv1 * g1.w;
        *(float4*)&ob[qb1 + c * 4] = o1;
    }
}

// ---------------------------------------------------------------------------
// Launch. Inputs: q_x, kv_x, tri_bias, mask_bias, mask(unused), Wq,Wk,Wv,Wg,Wo
// ---------------------------------------------------------------------------
extern "C" void kernel_launch(void* const* d_in, const int* in_sizes, int n_in,
                              void* d_out, int out_size)
{
    const float* q_x  = (const float*)d_in[0];
    const float* kv_x = (const float*)d_in[1];
    const float* tri  = (const float*)d_in[2];
    const float* mbp  = (const float*)d_in[3];
    const float* Wq   = (const float*)d_in[5];
    const float* Wk   = (const float*)d_in[6];
    const float* Wv   = (const float*)d_in[7];
    const float* Wg   = (const float*)d_in[8];
    const float* Wo   = (const float*)d_in[9];
    float* out = (float*)d_out;

    float *qb, *kb, *vb, *gb, *ob;
    cudaGetSymbolAddress((void**)&qb, g_qbuf);
    cudaGetSymbolAddress((void**)&kb, g_kbuf);
    cudaGetSymbolAddress((void**)&vb, g_vbuf);
    cudaGetSymbolAddress((void**)&gb, g_gbuf);
    cudaGetSymbolAddress((void**)&ob, g_obuf);

    const int grid = NROW / 128;  // 512
    const float qscale = 0.17677669529663687f;  // 1/sqrt(32)

    gemm128_kernel<<<grid, 256>>>(q_x,  Wq, qb, 1, qscale);
    gemm128_kernel<<<grid, 256>>>(kv_x, Wk, kb, 0, 1.f);
    gemm128_kernel<<<grid, 256>>>(kv_x, Wv, vb, 0, 1.f);
    gemm128_kernel<<<grid, 256>>>(q_x,  Wg, gb, 2, 1.f);

    attn_kernel<<<dim3(NSEQ, NHEAD), 128>>>(qb, kb, vb, gb, tri, mbp, ob);

    gemm128_kernel<<<grid, 256>>>(ob, Wo, out, 0, 1.f);
}

// round 9
// speedup vs baseline: 1.2695x; 1.2695x over previous
#include <cuda_runtime.h>
#include <cuda_bf16.h>
#include <math.h>
#include <stdint.h>

// Problem constants: B=1, N=256, Q=K=256, C=128, H=4, C_HID=32
#define NROW   65536
#define CDIM   128
#define NSEQ   256
#define NHEAD  4

// Scratch (allocation-free rule: __device__ globals)
__device__ float g_qbuf[(size_t)NROW * CDIM];
__device__ float g_kbuf[(size_t)NROW * CDIM];
__device__ float g_vbuf[(size_t)NROW * CDIM];
__device__ float g_gbuf[(size_t)NROW * CDIM];
__device__ float g_obuf[(size_t)NROW * CDIM];
// W in mma-B-fragment order, split bf16: [5 matrices][8192 u32]
// index: ((kstep*16 + ntile)*32 + lane)*2 + {0:b0, 1:b1}
__device__ uint32_t g_bfhi[5][8192];
__device__ uint32_t g_bflo[5][8192];

// ---------------------------------------------------------------------------
// bf16 split helpers
// ---------------------------------------------------------------------------
__device__ __forceinline__ uint32_t pack_bf2(float x0, float x1) {
    uint32_t r;
    asm("cvt.rn.bf16x2.f32 %0, %1, %2;" : "=r"(r) : "f"(x1), "f"(x0));
    return r;
}
// hi = bf16x2(x0,x1); lo = bf16x2 of residuals
__device__ __forceinline__ void split_bf2(float x0, float x1,
                                          uint32_t& hi, uint32_t& lo) {
    hi = pack_bf2(x0, x1);
    float h0 = __uint_as_float(hi << 16);
    float h1 = __uint_as_float(hi & 0xffff0000u);
    lo = pack_bf2(x0 - h0, x1 - h1);
}

__device__ __forceinline__ void mma_bf16(float c[4],
    uint32_t a0, uint32_t a1, uint32_t a2, uint32_t a3,
    uint32_t b0, uint32_t b1)
{
    asm("mma.sync.aligned.m16n8k16.row.col.f32.bf16.bf16.f32 "
        "{%0,%1,%2,%3}, {%4,%5,%6,%7}, {%8,%9}, {%0,%1,%2,%3};"
        : "+f"(c[0]), "+f"(c[1]), "+f"(c[2]), "+f"(c[3])
        : "r"(a0), "r"(a1), "r"(a2), "r"(a3), "r"(b0), "r"(b1));
}

// ---------------------------------------------------------------------------
// Weight prep: W[k][n] (5 matrices) -> split-bf16 B fragments in gmem.
// One thread per u64 fragment entry (4096 per matrix), blockIdx.y = matrix.
// mma B fragment (m16n8k16, col-major B = K-major W rows):
//   lane = n_in_tile*4 + k_quad;  b0 = W[k0..k0+1][n], b1 = W[k0+8..k0+9][n]
// ---------------------------------------------------------------------------
__global__ void wprep_kernel(const float* __restrict__ W0,
                             const float* __restrict__ W1,
                             const float* __restrict__ W2,
                             const float* __restrict__ W3,
                             const float* __restrict__ W4)
{
    const float* Wm[5] = {W0, W1, W2, W3, W4};
    const int mat = blockIdx.y;
    const float* W = Wm[mat];
    int i = blockIdx.x * 256 + threadIdx.x;      // 0..4095
    int lane = i & 31, t = i >> 5;
    int ntile = t & 15, kstep = t >> 4;
    int n  = ntile * 8 + (lane >> 2);
    int kb = kstep * 16 + (lane & 3) * 2;

    float w00 = W[kb * 128 + n];
    float w01 = W[(kb + 1) * 128 + n];
    float w10 = W[(kb + 8) * 128 + n];
    float w11 = W[(kb + 9) * 128 + n];

    uint32_t h0, l0, h1, l1;
    split_bf2(w00, w01, h0, l0);
    split_bf2(w10, w11, h1, l1);
    g_bfhi[mat][i * 2]     = h0;
    g_bfhi[mat][i * 2 + 1] = h1;
    g_bflo[mat][i * 2]     = l0;
    g_bflo[mat][i * 2 + 1] = l1;
}

// ---------------------------------------------------------------------------
// HMMA GEMM: Y[M,128] = epi( X[M,128] @ W[128,128] ).
// D = Xhi@Whi + Xlo@Whi + Xhi@Wlo, fp32 accum. No smem.
// 256 threads = 8 warps, each warp owns 16 M-rows; grid = M/128.
// op: 0 none, 1 scale alpha, 2 sigmoid
// ---------------------------------------------------------------------------
__global__ void __launch_bounds__(256) tc_gemm_kernel(
    const float* __restrict__ X,
    const uint32_t* __restrict__ Bhi,
    const uint32_t* __restrict__ Blo,
    float* __restrict__ Y, int op, float alpha)
{
    const int tid = threadIdx.x;
    const int w   = tid >> 5;
    const int l   = tid & 31;
    const int r0  = blockIdx.x * 128 + w * 16 + (l >> 2);
    const int r1  = r0 + 8;
    const int cq  = (l & 3) * 2;                 // col pair base within k16

    float acc[16][4];
#pragma unroll
    for (int nt = 0; nt < 16; nt++)
#pragma unroll
        for (int j = 0; j < 4; j++) acc[nt][j] = 0.f;

    const float* x0 = X + (size_t)r0 * 128;
    const float* x1 = X + (size_t)r1 * 128;
    const unsigned long long* bh64 = (const unsigned long long*)Bhi;
    const unsigned long long* bl64 = (const unsigned long long*)Blo;

#pragma unroll 4
    for (int ks = 0; ks < 8; ks++) {
        const int cb = ks * 16 + cq;
        float2 xa = *(const float2*)(x0 + cb);
        float2 xb = *(const float2*)(x1 + cb);
        float2 xc = *(const float2*)(x0 + cb + 8);
        float2 xd = *(const float2*)(x1 + cb + 8);
        uint32_t ah0, al0, ah1, al1, ah2, al2, ah3, al3;
        split_bf2(xa.x, xa.y, ah0, al0);
        split_bf2(xb.x, xb.y, ah1, al1);
        split_bf2(xc.x, xc.y, ah2, al2);
        split_bf2(xd.x, xd.y, ah3, al3);

        const unsigned long long* bh = bh64 + ks * 16 * 32 + l;
        const unsigned long long* bl = bl64 + ks * 16 * 32 + l;
#pragma unroll
        for (int nt = 0; nt < 16; nt++) {
            unsigned long long bhv = __ldg(bh + nt * 32);
            unsigned long long blv = __ldg(bl + nt * 32);
            uint32_t bh0 = (uint32_t)bhv, bh1 = (uint32_t)(bhv >> 32);
            uint32_t bl0 = (uint32_t)blv, bl1 = (uint32_t)(blv >> 32);
            mma_bf16(acc[nt], ah0, ah1, ah2, ah3, bh0, bh1);  // hi*hi
            mma_bf16(acc[nt], al0, al1, al2, al3, bh0, bh1);  // lo*hi
            mma_bf16(acc[nt], ah0, ah1, ah2, ah3, bl0, bl1);  // hi*lo
        }
    }

    // Epilogue: c0,c1 -> (r0, nt*8+cq, +1); c2,c3 -> (r1, ...)
    float* y0 = Y + (size_t)r0 * 128 + cq;
    float* y1 = Y + (size_t)r1 * 128 + cq;
#pragma unroll
    for (int nt = 0; nt < 16; nt++) {
        float2 p0 = make_float2(acc[nt][0], acc[nt][1]);
        float2 p1 = make_float2(acc[nt][2], acc[nt][3]);
        if (op == 1) {
            p0.x *= alpha; p0.y *= alpha; p1.x *= alpha; p1.y *= alpha;
        } else if (op == 2) {
            p0.x = 1.f / (1.f + __expf(-p0.x));
            p0.y = 1.f / (1.f + __expf(-p0.y));
            p1.x = 1.f / (1.f + __expf(-p1.x));
            p1.y = 1.f / (1.f + __expf(-p1.y));
        }
        *(float2*)(y0 + nt * 8) = p0;
        *(float2*)(y1 + nt * 8) = p1;
    }
}

// ---------------------------------------------------------------------------
// Attention (round-3 best): one CTA per (n,h), one thread per q row,
// chunked online softmax (chunk=8), f32x2 FMAs.
// ---------------------------------------------------------------------------
typedef unsigned long long ull;
__device__ __forceinline__ ull pk2(float lo, float hi) {
    ull r; asm("mov.b64 %0, {%1, %2};" : "=l"(r) : "f"(lo), "f"(hi)); return r;
}
__device__ __forceinline__ void upk2(ull v, float& lo, float& hi) {
    asm("mov.b64 {%0, %1}, %2;" : "=f"(lo), "=f"(hi) : "l"(v));
}
__device__ __forceinline__ ull ffma2(ull a, ull b, ull c) {
    ull d; asm("fma.rn.f32x2 %0, %1, %2, %3;" : "=l"(d) : "l"(a), "l"(b), "l"(c)); return d;
}
__device__ __forceinline__ ull fmul2(ull a, ull b) {
    ull d; asm("mul.rn.f32x2 %0, %1, %2;" : "=l"(d) : "l"(a), "l"(b)); return d;
}
union F4U2 { float4 f4; ull u2[2]; };

__global__ void __launch_bounds__(256) attn_kernel(
    const float* __restrict__ qb, const float* __restrict__ kb,
    const float* __restrict__ vb, const float* __restrict__ gb,
    const float* __restrict__ tri, const float* __restrict__ mb,
    float* __restrict__ ob)
{
    __shared__ float ks[128 * 32];
    __shared__ float vs[128 * 32];
    __shared__ float mbs[256];

    const int n   = blockIdx.x;
    const int h   = blockIdx.y;
    const int tid = threadIdx.x;
    const int qi  = tid;

    mbs[tid] = mb[(size_t)n * 256 + tid];

    const size_t qbase = ((size_t)(n * 256 + qi)) * 128 + h * 32;
    ull q2[16];
#pragma unroll
    for (int c = 0; c < 8; c++) {
        F4U2 t; t.f4 = *(const float4*)&qb[qbase + c * 4];
        q2[2 * c]     = t.u2[0];
        q2[2 * c + 1] = t.u2[1];
    }
    const float* trow = tri + ((size_t)(h * 256 + qi)) * 256;

    float m = -INFINITY, l = 0.f;
    ull acc[16];
#pragma unroll
    for (int c = 0; c < 16; c++) acc[c] = 0ull;

    for (int jt = 0; jt < 256; jt += 128) {
        __syncthreads();
        {
            const float4* kb4 = (const float4*)(kb + ((size_t)(n * 256 + jt)) * 128 + h * 32);
            const float4* vb4 = (const float4*)(vb + ((size_t)(n * 256 + jt)) * 128 + h * 32);
            float4* ks4 = (float4*)ks;
            float4* vs4 = (float4*)vs;
#pragma unroll
            for (int i = 0; i < 4; i++) {
                int idx = tid + 256 * i;
                int row = idx >> 3, c4 = idx & 7;
                ks4[idx] = kb4[row * 32 + c4];
                vs4[idx] = vb4[row * 32 + c4];
            }
        }
        __syncthreads();

        for (int jc = 0; jc < 128; jc += 8) {
            float s[8];
            float4 tb0 = *(const float4*)&trow[jt + jc];
            float4 tb1 = *(const float4*)&trow[jt + jc + 4];
            float tb[8] = {tb0.x, tb0.y, tb0.z, tb0.w, tb1.x, tb1.y, tb1.z, tb1.w};
#pragma unroll
            for (int u = 0; u < 8; u++) {
                const float4* kr = (const float4*)&ks[(jc + u) * 32];
                ull s2 = 0ull;
#pragma unroll
                for (int c = 0; c < 8; c++) {
                    F4U2 kk; kk.f4 = kr[c];
                    s2 = ffma2(q2[2 * c],     kk.u2[0], s2);
                    s2 = ffma2(q2[2 * c + 1], kk.u2[1], s2);
                }
                float lo, hi; upk2(s2, lo, hi);
                s[u] = lo + hi + tb[u] + mbs[jt + jc + u];
            }
            float cmax = s[0];
#pragma unroll
            for (int u = 1; u < 8; u++) cmax = fmaxf(cmax, s[u]);
            float mnew = fmaxf(m, cmax);
            float corr = __expf(m - mnew);
            m = mnew;
            l *= corr;
            ull c2 = pk2(corr, corr);
#pragma unroll
            for (int c = 0; c < 16; c++) acc[c] = fmul2(acc[c], c2);
#pragma unroll
            for (int u = 0; u < 8; u++) {
                float p = __expf(s[u] - m);
                l += p;
                ull p2 = pk2(p, p);
                const float4* vr = (const float4*)&vs[(jc + u) * 32];
#pragma unroll
                for (int c = 0; c < 8; c++) {
                    F4U2 vv; vv.f4 = vr[c];
                    acc[2 * c]     = ffma2(p2, vv.u2[0], acc[2 * c]);
                    acc[2 * c + 1] = ffma2(p2, vv.u2[1], acc[2 * c + 1]);
                }
            }
        }
    }

    const float inv = 1.f / l;
#pragma unroll
    for (int c = 0; c < 8; c++) {
        float4 gg = *(const float4*)&gb[qbase + c * 4];
        float a0, a1, a2, a3;
        upk2(acc[2 * c],     a0, a1);
        upk2(acc[2 * c + 1], a2, a3);
        float4 o;
        o.x = a0 * inv * gg.x;
        o.y = a1 * inv * gg.y;
        o.z = a2 * inv * gg.z;
        o.w = a3 * inv * gg.w;
        *(float4*)&ob[qbase + c * 4] = o;
    }
}

// ---------------------------------------------------------------------------
// Launch. Inputs: q_x, kv_x, tri_bias, mask_bias, mask(unused), Wq,Wk,Wv,Wg,Wo
// ---------------------------------------------------------------------------
extern "C" void kernel_launch(void* const* d_in, const int* in_sizes, int n_in,
                              void* d_out, int out_size)
{
    const float* q_x  = (const float*)d_in[0];
    const float* kv_x = (const float*)d_in[1];
    const float* tri  = (const float*)d_in[2];
    const float* mbp  = (const float*)d_in[3];
    float* out = (float*)d_out;

    float *qb, *kb, *vb, *gb, *ob;
    cudaGetSymbolAddress((void**)&qb, g_qbuf);
    cudaGetSymbolAddress((void**)&kb, g_kbuf);
    cudaGetSymbolAddress((void**)&vb, g_vbuf);
    cudaGetSymbolAddress((void**)&gb, g_gbuf);
    cudaGetSymbolAddress((void**)&ob, g_obuf);
    uint32_t *bfhi, *bflo;
    cudaGetSymbolAddress((void**)&bfhi, g_bfhi);
    cudaGetSymbolAddress((void**)&bflo, g_bflo);

    // Weight prep: all 5 matrices, fragment order, split bf16
    wprep_kernel<<<dim3(16, 5), 256>>>(
        (const float*)d_in[5], (const float*)d_in[6], (const float*)d_in[7],
        (const float*)d_in[8], (const float*)d_in[9]);

    const int grid = NROW / 128;  // 512
    const float qscale = 0.17677669529663687f;  // 1/sqrt(32)

    tc_gemm_kernel<<<grid, 256>>>(q_x,  bfhi + 0 * 8192, bflo + 0 * 8192, qb, 1, qscale);
    tc_gemm_kernel<<<grid, 256>>>(kv_x, bfhi + 1 * 8192, bflo + 1 * 8192, kb, 0, 1.f);
    tc_gemm_kernel<<<grid, 256>>>(kv_x, bfhi + 2 * 8192, bflo + 2 * 8192, vb, 0, 1.f);
    tc_gemm_kernel<<<grid, 256>>>(q_x,  bfhi + 3 * 8192, bflo + 3 * 8192, gb, 2, 1.f);

    attn_kernel<<<dim3(NSEQ, NHEAD), 256>>>(qb, kb, vb, gb, tri, mbp, ob);

    tc_gemm_kernel<<<grid, 256>>>(ob, bfhi + 4 * 8192, bflo + 4 * 8192, out, 0, 1.f);
}

// round 10
// speedup vs baseline: 1.5593x; 1.2283x over previous
#include <cuda_runtime.h>
#include <cuda_bf16.h>
#include <math.h>
#include <stdint.h>

// Problem constants: B=1, N=256, Q=K=256, C=128, H=4, C_HID=32
#define NROW   65536
#define CDIM   128
#define NSEQ   256
#define NHEAD  4

// Scratch (allocation-free rule: __device__ globals)
__device__ float g_qbuf[(size_t)NROW * CDIM];
__device__ float g_kbuf[(size_t)NROW * CDIM];
__device__ float g_vbuf[(size_t)NROW * CDIM];
__device__ float g_gbuf[(size_t)NROW * CDIM];
__device__ float g_obuf[(size_t)NROW * CDIM];
// W in mma-B-fragment order, split bf16: [5 matrices][8192 u32]
// u64 entry i = (b0,b1) for i = (kstep*16 + ntile)*32 + lane
__device__ uint32_t g_bfhi[5][8192];
__device__ uint32_t g_bflo[5][8192];

// ---------------------------------------------------------------------------
// bf16 split helpers
// ---------------------------------------------------------------------------
__device__ __forceinline__ uint32_t pack_bf2(float x0, float x1) {
    uint32_t r;
    asm("cvt.rn.bf16x2.f32 %0, %1, %2;" : "=r"(r) : "f"(x1), "f"(x0));
    return r;
}
__device__ __forceinline__ void split_bf2(float x0, float x1,
                                          uint32_t& hi, uint32_t& lo) {
    hi = pack_bf2(x0, x1);
    float h0 = __uint_as_float(hi << 16);
    float h1 = __uint_as_float(hi & 0xffff0000u);
    lo = pack_bf2(x0 - h0, x1 - h1);
}

__device__ __forceinline__ void mma_bf16(float c[4],
    uint32_t a0, uint32_t a1, uint32_t a2, uint32_t a3,
    uint32_t b0, uint32_t b1)
{
    asm("mma.sync.aligned.m16n8k16.row.col.f32.bf16.bf16.f32 "
        "{%0,%1,%2,%3}, {%4,%5,%6,%7}, {%8,%9}, {%0,%1,%2,%3};"
        : "+f"(c[0]), "+f"(c[1]), "+f"(c[2]), "+f"(c[3])
        : "r"(a0), "r"(a1), "r"(a2), "r"(a3), "r"(b0), "r"(b1));
}

// ---------------------------------------------------------------------------
// Weight prep: W[k][n] (5 matrices) -> split-bf16 B fragments in gmem.
// ---------------------------------------------------------------------------
__global__ void wprep_kernel(const float* __restrict__ W0,
                             const float* __restrict__ W1,
                             const float* __restrict__ W2,
                             const float* __restrict__ W3,
                             const float* __restrict__ W4)
{
    const float* Wm[5] = {W0, W1, W2, W3, W4};
    const int mat = blockIdx.y;
    const float* W = Wm[mat];
    int i = blockIdx.x * 256 + threadIdx.x;      // 0..4095
    int lane = i & 31, t = i >> 5;
    int ntile = t & 15, kstep = t >> 4;
    int n  = ntile * 8 + (lane >> 2);
    int kb = kstep * 16 + (lane & 3) * 2;

    float w00 = W[kb * 128 + n];
    float w01 = W[(kb + 1) * 128 + n];
    float w10 = W[(kb + 8) * 128 + n];
    float w11 = W[(kb + 9) * 128 + n];

    uint32_t h0, l0, h1, l1;
    split_bf2(w00, w01, h0, l0);
    split_bf2(w10, w11, h1, l1);
    g_bfhi[mat][i * 2]     = h0;
    g_bfhi[mat][i * 2 + 1] = h1;
    g_bflo[mat][i * 2]     = l0;
    g_bflo[mat][i * 2 + 1] = l1;
}

// ---------------------------------------------------------------------------
// HMMA GEMM: Y[M,128] = epi( X[M,128] @ W[128,128] ).
// D = Xhi@Whi + Xlo@Whi + Xhi@Wlo, fp32 accum.
// B staged in 64KB dynamic smem (whole split weight matrix), inner loop is
// LDS.64 with distance-1 software prefetch over the 16 n-tiles.
// 256 threads = 8 warps, each warp owns 16 M-rows; grid = M/128.
// op: 0 none, 1 scale alpha, 2 sigmoid
// ---------------------------------------------------------------------------
typedef unsigned long long ull;

__global__ void __launch_bounds__(256, 2) tc_gemm_kernel(
    const float* __restrict__ X,
    const uint32_t* __restrict__ Bhi,
    const uint32_t* __restrict__ Blo,
    float* __restrict__ Y, int op, float alpha)
{
    extern __shared__ ull sB[];                  // [2][4096]: hi then lo

    const int tid = threadIdx.x;
    const int w   = tid >> 5;
    const int l   = tid & 31;
    const int r0  = blockIdx.x * 128 + w * 16 + (l >> 2);
    const int r1  = r0 + 8;
    const int cq  = (l & 3) * 2;                 // col pair base within k16

    // Stage B: 4096 u64 hi + 4096 u64 lo (2048 uint4 loads total)
    {
        const uint4* bh4 = (const uint4*)Bhi;
        const uint4* bl4 = (const uint4*)Blo;
        uint4* s4h = (uint4*)sB;
        uint4* s4l = (uint4*)(sB + 4096);
#pragma unroll
        for (int i = 0; i < 8; i++) {
            s4h[tid + 256 * i] = bh4[tid + 256 * i];
            s4l[tid + 256 * i] = bl4[tid + 256 * i];
        }
    }

    float acc[16][4];
#pragma unroll
    for (int nt = 0; nt < 16; nt++)
#pragma unroll
        for (int j = 0; j < 4; j++) acc[nt][j] = 0.f;

    const float* x0 = X + (size_t)r0 * 128;
    const float* x1 = X + (size_t)r1 * 128;

    __syncthreads();

#pragma unroll
    for (int ks = 0; ks < 8; ks++) {
        const int cb = ks * 16 + cq;
        float2 xa = *(const float2*)(x0 + cb);
        float2 xb = *(const float2*)(x1 + cb);
        float2 xc = *(const float2*)(x0 + cb + 8);
        float2 xd = *(const float2*)(x1 + cb + 8);
        uint32_t ah0, al0, ah1, al1, ah2, al2, ah3, al3;
        split_bf2(xa.x, xa.y, ah0, al0);
        split_bf2(xb.x, xb.y, ah1, al1);
        split_bf2(xc.x, xc.y, ah2, al2);
        split_bf2(xd.x, xd.y, ah3, al3);

        const ull* bh = sB + ks * 512 + l;       // stride 32 u64 per nt
        const ull* bl = bh + 4096;

        ull hcur = bh[0], lcur = bl[0];
#pragma unroll
        for (int nt = 0; nt < 16; nt++) {
            ull hnxt = 0, lnxt = 0;
            if (nt < 15) {
                hnxt = bh[(nt + 1) * 32];
                lnxt = bl[(nt + 1) * 32];
            }
            uint32_t bh0 = (uint32_t)hcur, bh1 = (uint32_t)(hcur >> 32);
            uint32_t bl0 = (uint32_t)lcur, bl1 = (uint32_t)(lcur >> 32);
            mma_bf16(acc[nt], ah0, ah1, ah2, ah3, bh0, bh1);  // hi*hi
            mma_bf16(acc[nt], al0, al1, al2, al3, bh0, bh1);  // lo*hi
            mma_bf16(acc[nt], ah0, ah1, ah2, ah3, bl0, bl1);  // hi*lo
            hcur = hnxt; lcur = lnxt;
        }
    }

    // Epilogue: c0,c1 -> (r0, nt*8+cq, +1); c2,c3 -> (r1, ...)
    float* y0 = Y + (size_t)r0 * 128 + cq;
    float* y1 = Y + (size_t)r1 * 128 + cq;
#pragma unroll
    for (int nt = 0; nt < 16; nt++) {
        float2 p0 = make_float2(acc[nt][0], acc[nt][1]);
        float2 p1 = make_float2(acc[nt][2], acc[nt][3]);
        if (op == 1) {
            p0.x *= alpha; p0.y *= alpha; p1.x *= alpha; p1.y *= alpha;
        } else if (op == 2) {
            p0.x = 1.f / (1.f + __expf(-p0.x));
            p0.y = 1.f / (1.f + __expf(-p0.y));
            p1.x = 1.f / (1.f + __expf(-p1.x));
            p1.y = 1.f / (1.f + __expf(-p1.y));
        }
        *(float2*)(y0 + nt * 8) = p0;
        *(float2*)(y1 + nt * 8) = p1;
    }
}

// ---------------------------------------------------------------------------
// Attention (round-3 best): one CTA per (n,h), one thread per q row,
// chunked online softmax (chunk=8), f32x2 FMAs.
// ---------------------------------------------------------------------------
__device__ __forceinline__ ull pk2(float lo, float hi) {
    ull r; asm("mov.b64 %0, {%1, %2};" : "=l"(r) : "f"(lo), "f"(hi)); return r;
}
__device__ __forceinline__ void upk2(ull v, float& lo, float& hi) {
    asm("mov.b64 {%0, %1}, %2;" : "=f"(lo), "=f"(hi) : "l"(v));
}
__device__ __forceinline__ ull ffma2(ull a, ull b, ull c) {
    ull d; asm("fma.rn.f32x2 %0, %1, %2, %3;" : "=l"(d) : "l"(a), "l"(b), "l"(c)); return d;
}
__device__ __forceinline__ ull fmul2(ull a, ull b) {
    ull d; asm("mul.rn.f32x2 %0, %1, %2;" : "=l"(d) : "l"(a), "l"(b)); return d;
}
union F4U2 { float4 f4; ull u2[2]; };

__global__ void __launch_bounds__(256) attn_kernel(
    const float* __restrict__ qb, const float* __restrict__ kb,
    const float* __restrict__ vb, const float* __restrict__ gb,
    const float* __restrict__ tri, const float* __restrict__ mb,
    float* __restrict__ ob)
{
    __shared__ float ks[128 * 32];
    __shared__ float vs[128 * 32];
    __shared__ float mbs[256];

    const int n   = blockIdx.x;
    const int h   = blockIdx.y;
    const int tid = threadIdx.x;
    const int qi  = tid;

    mbs[tid] = mb[(size_t)n * 256 + tid];

    const size_t qbase = ((size_t)(n * 256 + qi)) * 128 + h * 32;
    ull q2[16];
#pragma unroll
    for (int c = 0; c < 8; c++) {
        F4U2 t; t.f4 = *(const float4*)&qb[qbase + c * 4];
        q2[2 * c]     = t.u2[0];
        q2[2 * c + 1] = t.u2[1];
    }
    const float* trow = tri + ((size_t)(h * 256 + qi)) * 256;

    float m = -INFINITY, l = 0.f;
    ull acc[16];
#pragma unroll
    for (int c = 0; c < 16; c++) acc[c] = 0ull;

    for (int jt = 0; jt < 256; jt += 128) {
        __syncthreads();
        {
            const float4* kb4 = (const float4*)(kb + ((size_t)(n * 256 + jt)) * 128 + h * 32);
            const float4* vb4 = (const float4*)(vb + ((size_t)(n * 256 + jt)) * 128 + h * 32);
            float4* ks4 = (float4*)ks;
            float4* vs4 = (float4*)vs;
#pragma unroll
            for (int i = 0; i < 4; i++) {
                int idx = tid + 256 * i;
                int row = idx >> 3, c4 = idx & 7;
                ks4[idx] = kb4[row * 32 + c4];
                vs4[idx] = vb4[row * 32 + c4];
            }
        }
        __syncthreads();

        for (int jc = 0; jc < 128; jc += 8) {
            float s[8];
            float4 tb0 = *(const float4*)&trow[jt + jc];
            float4 tb1 = *(const float4*)&trow[jt + jc + 4];
            float tb[8] = {tb0.x, tb0.y, tb0.z, tb0.w, tb1.x, tb1.y, tb1.z, tb1.w};
#pragma unroll
            for (int u = 0; u < 8; u++) {
                const float4* kr = (const float4*)&ks[(jc + u) * 32];
                ull s2 = 0ull;
#pragma unroll
                for (int c = 0; c < 8; c++) {
                    F4U2 kk; kk.f4 = kr[c];
                    s2 = ffma2(q2[2 * c],     kk.u2[0], s2);
                    s2 = ffma2(q2[2 * c + 1], kk.u2[1], s2);
                }
                float lo, hi; upk2(s2, lo, hi);
                s[u] = lo + hi + tb[u] + mbs[jt + jc + u];
            }
            float cmax = s[0];
#pragma unroll
            for (int u = 1; u < 8; u++) cmax = fmaxf(cmax, s[u]);
            float mnew = fmaxf(m, cmax);
            float corr = __expf(m - mnew);
            m = mnew;
            l *= corr;
            ull c2 = pk2(corr, corr);
#pragma unroll
            for (int c = 0; c < 16; c++) acc[c] = fmul2(acc[c], c2);
#pragma unroll
            for (int u = 0; u < 8; u++) {
                float p = __expf(s[u] - m);
                l += p;
                ull p2 = pk2(p, p);
                const float4* vr = (const float4*)&vs[(jc + u) * 32];
#pragma unroll
                for (int c = 0; c < 8; c++) {
                    F4U2 vv; vv.f4 = vr[c];
                    acc[2 * c]     = ffma2(p2, vv.u2[0], acc[2 * c]);
                    acc[2 * c + 1] = ffma2(p2, vv.u2[1], acc[2 * c + 1]);
                }
            }
        }
    }

    const float inv = 1.f / l;
#pragma unroll
    for (int c = 0; c < 8; c++) {
        float4 gg = *(const float4*)&gb[qbase + c * 4];
        float a0, a1, a2, a3;
        upk2(acc[2 * c],     a0, a1);
        upk2(acc[2 * c + 1], a2, a3);
        float4 o;
        o.x = a0 * inv * gg.x;
        o.y = a1 * inv * gg.y;
        o.z = a2 * inv * gg.z;
        o.w = a3 * inv * gg.w;
        *(float4*)&ob[qbase + c * 4] = o;
    }
}

// ---------------------------------------------------------------------------
// Launch. Inputs: q_x, kv_x, tri_bias, mask_bias, mask(unused), Wq,Wk,Wv,Wg,Wo
// ---------------------------------------------------------------------------
extern "C" void kernel_launch(void* const* d_in, const int* in_sizes, int n_in,
                              void* d_out, int out_size)
{
    const float* q_x  = (const float*)d_in[0];
    const float* kv_x = (const float*)d_in[1];
    const float* tri  = (const float*)d_in[2];
    const float* mbp  = (const float*)d_in[3];
    float* out = (float*)d_out;

    float *qb, *kb, *vb, *gb, *ob;
    cudaGetSymbolAddress((void**)&qb, g_qbuf);
    cudaGetSymbolAddress((void**)&kb, g_kbuf);
    cudaGetSymbolAddress((void**)&vb, g_vbuf);
    cudaGetSymbolAddress((void**)&gb, g_gbuf);
    cudaGetSymbolAddress((void**)&ob, g_obuf);
    uint32_t *bfhi, *bflo;
    cudaGetSymbolAddress((void**)&bfhi, g_bfhi);
    cudaGetSymbolAddress((void**)&bflo, g_bflo);

    static int smem_set = -1;
    if (smem_set < 0) {
        cudaFuncSetAttribute(tc_gemm_kernel,
                             cudaFuncAttributeMaxDynamicSharedMemorySize, 65536);
        smem_set = 1;
    }

    // Weight prep: all 5 matrices, fragment order, split bf16
    wprep_kernel<<<dim3(16, 5), 256>>>(
        (const float*)d_in[5], (const float*)d_in[6], (const float*)d_in[7],
        (const float*)d_in[8], (const float*)d_in[9]);

    const int grid = NROW / 128;  // 512
    const float qscale = 0.17677669529663687f;  // 1/sqrt(32)

    tc_gemm_kernel<<<grid, 256, 65536>>>(q_x,  bfhi + 0 * 8192, bflo + 0 * 8192, qb, 1, qscale);
    tc_gemm_kernel<<<grid, 256, 65536>>>(kv_x, bfhi + 1 * 8192, bflo + 1 * 8192, kb, 0, 1.f);
    tc_gemm_kernel<<<grid, 256, 65536>>>(kv_x, bfhi + 2 * 8192, bflo + 2 * 8192, vb, 0, 1.f);
    tc_gemm_kernel<<<grid, 256, 65536>>>(q_x,  bfhi + 3 * 8192, bflo + 3 * 8192, gb, 2, 1.f);

    attn_kernel<<<dim3(NSEQ, NHEAD), 256>>>(qb, kb, vb, gb, tri, mbp, ob);

    tc_gemm_kernel<<<grid, 256, 65536>>>(ob, bfhi + 4 * 8192, bflo + 4 * 8192, out, 0, 1.f);
}

// round 14
// speedup vs baseline: 2.5670x; 1.6463x over previous
#include <cuda_runtime.h>
#include <cuda_bf16.h>
#include <math.h>
#include <stdint.h>

// Problem constants: B=1, N=256, Q=K=256, C=128, H=4, C_HID=32
#define NROW   65536
#define CDIM   128
#define NSEQ   256
#define NHEAD  4

// Scratch (allocation-free rule: __device__ globals)
__device__ float g_qbuf[(size_t)NROW * CDIM];
__device__ float g_kbuf[(size_t)NROW * CDIM];
__device__ float g_vbuf[(size_t)NROW * CDIM];
__device__ float g_gbuf[(size_t)NROW * CDIM];
__device__ float g_obuf[(size_t)NROW * CDIM];
// W in mma-B-fragment order, split bf16: [5 matrices][8192 u32]
__device__ uint32_t g_bfhi[5][8192];
__device__ uint32_t g_bflo[5][8192];

typedef unsigned long long ull;

// ---------------------------------------------------------------------------
// bf16 split helpers
// ---------------------------------------------------------------------------
__device__ __forceinline__ uint32_t pack_bf2(float x0, float x1) {
    uint32_t r;
    asm("cvt.rn.bf16x2.f32 %0, %1, %2;" : "=r"(r) : "f"(x1), "f"(x0));
    return r;
}
__device__ __forceinline__ void split_bf2(float x0, float x1,
                                          uint32_t& hi, uint32_t& lo) {
    hi = pack_bf2(x0, x1);
    float h0 = __uint_as_float(hi << 16);
    float h1 = __uint_as_float(hi & 0xffff0000u);
    lo = pack_bf2(x0 - h0, x1 - h1);
}

__device__ __forceinline__ void mma_bf16(float c[4],
    uint32_t a0, uint32_t a1, uint32_t a2, uint32_t a3,
    uint32_t b0, uint32_t b1)
{
    asm("mma.sync.aligned.m16n8k16.row.col.f32.bf16.bf16.f32 "
        "{%0,%1,%2,%3}, {%4,%5,%6,%7}, {%8,%9}, {%0,%1,%2,%3};"
        : "+f"(c[0]), "+f"(c[1]), "+f"(c[2]), "+f"(c[3])
        : "r"(a0), "r"(a1), "r"(a2), "r"(a3), "r"(b0), "r"(b1));
}

// ---------------------------------------------------------------------------
// Weight prep: W[k][n] (5 matrices) -> split-bf16 B fragments in gmem.
// ---------------------------------------------------------------------------
__global__ void wprep_kernel(const float* __restrict__ W0,
                             const float* __restrict__ W1,
                             const float* __restrict__ W2,
                             const float* __restrict__ W3,
                             const float* __restrict__ W4)
{
    const float* Wm[5] = {W0, W1, W2, W3, W4};
    const int mat = blockIdx.y;
    const float* W = Wm[mat];
    int i = blockIdx.x * 256 + threadIdx.x;      // 0..4095
    int lane = i & 31, t = i >> 5;
    int ntile = t & 15, kstep = t >> 4;
    int n  = ntile * 8 + (lane >> 2);
    int kb = kstep * 16 + (lane & 3) * 2;

    float w00 = W[kb * 128 + n];
    float w01 = W[(kb + 1) * 128 + n];
    float w10 = W[(kb + 8) * 128 + n];
    float w11 = W[(kb + 9) * 128 + n];

    uint32_t h0, l0, h1, l1;
    split_bf2(w00, w01, h0, l0);
    split_bf2(w10, w11, h1, l1);
    g_bfhi[mat][i * 2]     = h0;
    g_bfhi[mat][i * 2 + 1] = h1;
    g_bflo[mat][i * 2]     = l0;
    g_bflo[mat][i * 2 + 1] = l1;
}

// ---------------------------------------------------------------------------
// HMMA GEMM (round-10, measured 25.8us): Y = epi(X @ W), split-bf16 3-term.
// B staged in 64KB dynamic smem; dist-1 prefetch over 16 n-tiles.
// ---------------------------------------------------------------------------
__global__ void __launch_bounds__(256, 2) tc_gemm_kernel(
    const float* __restrict__ X,
    const uint32_t* __restrict__ Bhi,
    const uint32_t* __restrict__ Blo,
    float* __restrict__ Y, int op, float alpha)
{
    extern __shared__ ull sB[];                  // [2][4096]: hi then lo

    const int tid = threadIdx.x;
    const int w   = tid >> 5;
    const int l   = tid & 31;
    const int r0  = blockIdx.x * 128 + w * 16 + (l >> 2);
    const int r1  = r0 + 8;
    const int cq  = (l & 3) * 2;

    {
        const uint4* bh4 = (const uint4*)Bhi;
        const uint4* bl4 = (const uint4*)Blo;
        uint4* s4h = (uint4*)sB;
        uint4* s4l = (uint4*)(sB + 4096);
#pragma unroll
        for (int i = 0; i < 8; i++) {
            s4h[tid + 256 * i] = bh4[tid + 256 * i];
            s4l[tid + 256 * i] = bl4[tid + 256 * i];
        }
    }

    float acc[16][4];
#pragma unroll
    for (int nt = 0; nt < 16; nt++)
#pragma unroll
        for (int j = 0; j < 4; j++) acc[nt][j] = 0.f;

    const float* x0 = X + (size_t)r0 * 128;
    const float* x1 = X + (size_t)r1 * 128;

    __syncthreads();

#pragma unroll
    for (int ks = 0; ks < 8; ks++) {
        const int cb = ks * 16 + cq;
        float2 xa = *(const float2*)(x0 + cb);
        float2 xb = *(const float2*)(x1 + cb);
        float2 xc = *(const float2*)(x0 + cb + 8);
        float2 xd = *(const float2*)(x1 + cb + 8);
        uint32_t ah0, al0, ah1, al1, ah2, al2, ah3, al3;
        split_bf2(xa.x, xa.y, ah0, al0);
        split_bf2(xb.x, xb.y, ah1, al1);
        split_bf2(xc.x, xc.y, ah2, al2);
        split_bf2(xd.x, xd.y, ah3, al3);

        const ull* bh = sB + ks * 512 + l;
        const ull* bl = bh + 4096;

        ull hcur = bh[0], lcur = bl[0];
#pragma unroll
        for (int nt = 0; nt < 16; nt++) {
            ull hnxt = 0, lnxt = 0;
            if (nt < 15) {
                hnxt = bh[(nt + 1) * 32];
                lnxt = bl[(nt + 1) * 32];
            }
            uint32_t bh0 = (uint32_t)hcur, bh1 = (uint32_t)(hcur >> 32);
            uint32_t bl0 = (uint32_t)lcur, bl1 = (uint32_t)(lcur >> 32);
            mma_bf16(acc[nt], ah0, ah1, ah2, ah3, bh0, bh1);
            mma_bf16(acc[nt], al0, al1, al2, al3, bh0, bh1);
            mma_bf16(acc[nt], ah0, ah1, ah2, ah3, bl0, bl1);
            hcur = hnxt; lcur = lnxt;
        }
    }

    float* y0 = Y + (size_t)r0 * 128 + cq;
    float* y1 = Y + (size_t)r1 * 128 + cq;
#pragma unroll
    for (int nt = 0; nt < 16; nt++) {
        float2 p0 = make_float2(acc[nt][0], acc[nt][1]);
        float2 p1 = make_float2(acc[nt][2], acc[nt][3]);
        if (op == 1) {
            p0.x *= alpha; p0.y *= alpha; p1.x *= alpha; p1.y *= alpha;
        } else if (op == 2) {
            p0.x = 1.f / (1.f + __expf(-p0.x));
            p0.y = 1.f / (1.f + __expf(-p0.y));
            p1.x = 1.f / (1.f + __expf(-p1.x));
            p1.y = 1.f / (1.f + __expf(-p1.y));
        }
        *(float2*)(y0 + nt * 8) = p0;
        *(float2*)(y1 + nt * 8) = p1;
    }
}

// ---------------------------------------------------------------------------
// HMMA flash attention: CTA per (n,h), 8 warps x 32 q-rows, K tiles of 64.
// S = Qhi@Khi + Qlo@Khi + Qhi@Klo (bias preloaded in accumulator).
// P@V = Phi@Vhi + Plo@Vhi + Phi@Vlo. Online softmax in fragment layout.
// K smem: [key][dimpair] stride 20 u32; V smem: [col][keypair] stride 36 u32
// -> inner LDS.32 conflict-free.
// R11 bug fixed: K staging now covers ALL 32 channels (it-loop, g2 = g+4*it).
// ---------------------------------------------------------------------------
__global__ void __launch_bounds__(256) attn_mma_kernel(
    const float* __restrict__ qb, const float* __restrict__ kb,
    const float* __restrict__ vb, const float* __restrict__ gb,
    const float* __restrict__ tri, const float* __restrict__ mb,
    float* __restrict__ ob)
{
    __shared__ uint32_t s_khi[64 * 20], s_klo[64 * 20];   // 5120B each
    __shared__ uint32_t s_vhi[32 * 36], s_vlo[32 * 36];   // 4608B each
    __shared__ float    s_mb[256];

    const int n   = blockIdx.x;
    const int h   = blockIdx.y;
    const int tid = threadIdx.x;
    const int w   = tid >> 5;
    const int l   = tid & 31;
    const int lq  = l >> 2;     // 0..7
    const int lc  = l & 3;      // 0..3
    const int wb  = w * 32;     // warp's q-row base

    s_mb[tid] = mb[(size_t)n * 256 + tid];

    // ---- Q fragments (split bf16): [mtile][kstep][a0..a3] ----
    uint32_t qh[2][2][4], ql[2][2][4];
#pragma unroll
    for (int mt = 0; mt < 2; mt++) {
        const int rA = wb + mt * 16 + lq;
        const int rB = rA + 8;
        const float* qA = qb + ((size_t)(n * 256 + rA)) * 128 + h * 32;
        const float* qB = qb + ((size_t)(n * 256 + rB)) * 128 + h * 32;
#pragma unroll
        for (int ks = 0; ks < 2; ks++) {
            const int k0 = ks * 16 + lc * 2;
            float2 x0 = *(const float2*)(qA + k0);
            float2 x1 = *(const float2*)(qB + k0);
            float2 x2 = *(const float2*)(qA + k0 + 8);
            float2 x3 = *(const float2*)(qB + k0 + 8);
            split_bf2(x0.x, x0.y, qh[mt][ks][0], ql[mt][ks][0]);
            split_bf2(x1.x, x1.y, qh[mt][ks][1], ql[mt][ks][1]);
            split_bf2(x2.x, x2.y, qh[mt][ks][2], ql[mt][ks][2]);
            split_bf2(x3.x, x3.y, qh[mt][ks][3], ql[mt][ks][3]);
        }
    }

    float oa[2][4][4];
#pragma unroll
    for (int mt = 0; mt < 2; mt++)
#pragma unroll
        for (int nt = 0; nt < 4; nt++)
#pragma unroll
            for (int j = 0; j < 4; j++) oa[mt][nt][j] = 0.f;
    float mrun[2][2] = {{-INFINITY, -INFINITY}, {-INFINITY, -INFINITY}};
    float lrun[2][2] = {{0.f, 0.f}, {0.f, 0.f}};

    for (int jt = 0; jt < 256; jt += 64) {
        __syncthreads();
        // ---- stage K tile: 64 keys x 32 dims -> split pairs, stride 20 ----
        // Each key has 4 threads; each loads TWO float4s (g2 = g, g+4) so all
        // 16 channel-pairs (32 channels) are populated.
        {
            const int key = tid >> 2, g = tid & 3;
            const float* kr = kb + ((size_t)(n * 256 + jt + key)) * 128 + h * 32;
#pragma unroll
            for (int it = 0; it < 2; it++) {
                const int g2 = g + 4 * it;            // 0..7
                float4 kv = *(const float4*)(kr + 4 * g2);
                uint32_t h0, l0, h1, l1;
                split_bf2(kv.x, kv.y, h0, l0);
                split_bf2(kv.z, kv.w, h1, l1);
                s_khi[key * 20 + 2 * g2]     = h0;
                s_khi[key * 20 + 2 * g2 + 1] = h1;
                s_klo[key * 20 + 2 * g2]     = l0;
                s_klo[key * 20 + 2 * g2 + 1] = l1;
            }
        }
        // ---- stage V tile transposed: [col][keypair], stride 36 ----
#pragma unroll
        for (int it = 0; it < 2; it++) {
            const int idx = tid + 256 * it;           // 0..511
            const int kp = idx >> 4, c = (idx & 15) * 2;
            const float* v0 = vb + ((size_t)(n * 256 + jt + 2 * kp)) * 128 + h * 32 + c;
            float2 a = *(const float2*)v0;
            float2 b = *(const float2*)(v0 + 128);
            uint32_t h0, l0, h1, l1;
            split_bf2(a.x, b.x, h0, l0);              // col c, keys 2kp,2kp+1
            split_bf2(a.y, b.y, h1, l1);              // col c+1
            s_vhi[c * 36 + kp]       = h0;
            s_vlo[c * 36 + kp]       = l0;
            s_vhi[(c + 1) * 36 + kp] = h1;
            s_vlo[(c + 1) * 36 + kp] = l1;
        }
        __syncthreads();

#pragma unroll
        for (int mt = 0; mt < 2; mt++) {
            const int rA = wb + mt * 16 + lq;
            const int rB = rA + 8;
            const float* tA = tri + ((size_t)(h * 256 + rA)) * 256 + jt;
            const float* tB = tri + ((size_t)(h * 256 + rB)) * 256 + jt;

            // ---- S accumulators preloaded with bias ----
            float sc[8][4];
#pragma unroll
            for (int nt = 0; nt < 8; nt++) {
                const int col = nt * 8 + lc * 2;
                float2 bA = *(const float2*)(tA + col);
                float2 bB = *(const float2*)(tB + col);
                float2 mv = *(const float2*)&s_mb[jt + col];
                sc[nt][0] = bA.x + mv.x; sc[nt][1] = bA.y + mv.y;
                sc[nt][2] = bB.x + mv.x; sc[nt][3] = bB.y + mv.y;
            }
            // ---- S += Q K^T (3-term split) ----
#pragma unroll
            for (int nt = 0; nt < 8; nt++) {
                const uint32_t* kh = &s_khi[(nt * 8 + lq) * 20];
                const uint32_t* kl = &s_klo[(nt * 8 + lq) * 20];
#pragma unroll
                for (int ks = 0; ks < 2; ks++) {
                    uint32_t b0h = kh[ks * 8 + lc], b1h = kh[ks * 8 + 4 + lc];
                    uint32_t b0l = kl[ks * 8 + lc], b1l = kl[ks * 8 + 4 + lc];
                    mma_bf16(sc[nt], qh[mt][ks][0], qh[mt][ks][1],
                             qh[mt][ks][2], qh[mt][ks][3], b0h, b1h);
                    mma_bf16(sc[nt], ql[mt][ks][0], ql[mt][ks][1],
                             ql[mt][ks][2], ql[mt][ks][3], b0h, b1h);
                    mma_bf16(sc[nt], qh[mt][ks][0], qh[mt][ks][1],
                             qh[mt][ks][2], qh[mt][ks][3], b0l, b1l);
                }
            }
            // ---- online softmax (rows A, B) ----
            float mxA = sc[0][0], mxB = sc[0][2];
#pragma unroll
            for (int nt = 0; nt < 8; nt++) {
                mxA = fmaxf(mxA, fmaxf(sc[nt][0], sc[nt][1]));
                mxB = fmaxf(mxB, fmaxf(sc[nt][2], sc[nt][3]));
            }
            mxA = fmaxf(mxA, __shfl_xor_sync(0xffffffffu, mxA, 1));
            mxA = fmaxf(mxA, __shfl_xor_sync(0xffffffffu, mxA, 2));
            mxB = fmaxf(mxB, __shfl_xor_sync(0xffffffffu, mxB, 1));
            mxB = fmaxf(mxB, __shfl_xor_sync(0xffffffffu, mxB, 2));
            float mnA = fmaxf(mrun[mt][0], mxA);
            float mnB = fmaxf(mrun[mt][1], mxB);
            float corrA = __expf(mrun[mt][0] - mnA);
            float corrB = __expf(mrun[mt][1] - mnB);
            mrun[mt][0] = mnA; mrun[mt][1] = mnB;
            float sumA = 0.f, sumB = 0.f;
#pragma unroll
            for (int nt = 0; nt < 8; nt++) {
                sc[nt][0] = __expf(sc[nt][0] - mnA);
                sc[nt][1] = __expf(sc[nt][1] - mnA);
                sc[nt][2] = __expf(sc[nt][2] - mnB);
                sc[nt][3] = __expf(sc[nt][3] - mnB);
                sumA += sc[nt][0] + sc[nt][1];
                sumB += sc[nt][2] + sc[nt][3];
            }
            lrun[mt][0] = lrun[mt][0] * corrA + sumA;
            lrun[mt][1] = lrun[mt][1] * corrB + sumB;
#pragma unroll
            for (int nt = 0; nt < 4; nt++) {
                oa[mt][nt][0] *= corrA; oa[mt][nt][1] *= corrA;
                oa[mt][nt][2] *= corrB; oa[mt][nt][3] *= corrB;
            }
            // ---- O += P V (3-term split) ----
#pragma unroll
            for (int ks = 0; ks < 4; ks++) {
                uint32_t ph[4], pl[4];
                split_bf2(sc[2 * ks][0],     sc[2 * ks][1],     ph[0], pl[0]);
                split_bf2(sc[2 * ks][2],     sc[2 * ks][3],     ph[1], pl[1]);
                split_bf2(sc[2 * ks + 1][0], sc[2 * ks + 1][1], ph[2], pl[2]);
                split_bf2(sc[2 * ks + 1][2], sc[2 * ks + 1][3], ph[3], pl[3]);
#pragma unroll
                for (int nt = 0; nt < 4; nt++) {
                    const uint32_t* vh = &s_vhi[(nt * 8 + lq) * 36];
                    const uint32_t* vl = &s_vlo[(nt * 8 + lq) * 36];
                    uint32_t b0h = vh[ks * 8 + lc], b1h = vh[ks * 8 + 4 + lc];
                    uint32_t b0l = vl[ks * 8 + lc], b1l = vl[ks * 8 + 4 + lc];
                    mma_bf16(oa[mt][nt], ph[0], ph[1], ph[2], ph[3], b0h, b1h);
                    mma_bf16(oa[mt][nt], pl[0], pl[1], pl[2], pl[3], b0h, b1h);
                    mma_bf16(oa[mt][nt], ph[0], ph[1], ph[2], ph[3], b0l, b1l);
                }
            }
        }
    }

    // ---- epilogue: normalize, gate, store ----
#pragma unroll
    for (int mt = 0; mt < 2; mt++) {
        float lA = lrun[mt][0], lB = lrun[mt][1];
        lA += __shfl_xor_sync(0xffffffffu, lA, 1);
        lA += __shfl_xor_sync(0xffffffffu, lA, 2);
        lB += __shfl_xor_sync(0xffffffffu, lB, 1);
        lB += __shfl_xor_sync(0xffffffffu, lB, 2);
        const float invA = 1.f / lA, invB = 1.f / lB;
        const int rA = wb + mt * 16 + lq;
        const int rB = rA + 8;
        const float* gA = gb + ((size_t)(n * 256 + rA)) * 128 + h * 32;
        const float* gB = gb + ((size_t)(n * 256 + rB)) * 128 + h * 32;
        float* oA = ob + ((size_t)(n * 256 + rA)) * 128 + h * 32;
        float* oB = ob + ((size_t)(n * 256 + rB)) * 128 + h * 32;
#pragma unroll
        for (int nt = 0; nt < 4; nt++) {
            const int col = nt * 8 + lc * 2;
            float2 ga = *(const float2*)(gA + col);
            float2 gc = *(const float2*)(gB + col);
            float2 o0, o1;
            o0.x = oa[mt][nt][0] * invA * ga.x;
            o0.y = oa[mt][nt][1] * invA * ga.y;
            o1.x = oa[mt][nt][2] * invB * gc.x;
            o1.y = oa[mt][nt][3] * invB * gc.y;
            *(float2*)(oA + col) = o0;
            *(float2*)(oB + col) = o1;
        }
    }
}

// ---------------------------------------------------------------------------
// Launch. Inputs: q_x, kv_x, tri_bias, mask_bias, mask(unused), Wq,Wk,Wv,Wg,Wo
// ---------------------------------------------------------------------------
extern "C" void kernel_launch(void* const* d_in, const int* in_sizes, int n_in,
                              void* d_out, int out_size)
{
    const float* q_x  = (const float*)d_in[0];
    const float* kv_x = (const float*)d_in[1];
    const float* tri  = (const float*)d_in[2];
    const float* mbp  = (const float*)d_in[3];
    float* out = (float*)d_out;

    float *qb, *kb, *vb, *gb, *ob;
    cudaGetSymbolAddress((void**)&qb, g_qbuf);
    cudaGetSymbolAddress((void**)&kb, g_kbuf);
    cudaGetSymbolAddress((void**)&vb, g_vbuf);
    cudaGetSymbolAddress((void**)&gb, g_gbuf);
    cudaGetSymbolAddress((void**)&ob, g_obuf);
    uint32_t *bfhi, *bflo;
    cudaGetSymbolAddress((void**)&bfhi, g_bfhi);
    cudaGetSymbolAddress((void**)&bflo, g_bflo);

    static int smem_set = -1;
    if (smem_set < 0) {
        cudaFuncSetAttribute(tc_gemm_kernel,
                             cudaFuncAttributeMaxDynamicSharedMemorySize, 65536);
        smem_set = 1;
    }

    wprep_kernel<<<dim3(16, 5), 256>>>(
        (const float*)d_in[5], (const float*)d_in[6], (const float*)d_in[7],
        (const float*)d_in[8], (const float*)d_in[9]);

    const int grid = NROW / 128;  // 512
    const float qscale = 0.17677669529663687f;  // 1/sqrt(32)

    tc_gemm_kernel<<<grid, 256, 65536>>>(q_x,  bfhi + 0 * 8192, bflo + 0 * 8192, qb, 1, qscale);
    tc_gemm_kernel<<<grid, 256, 65536>>>(kv_x, bfhi + 1 * 8192, bflo + 1 * 8192, kb, 0, 1.f);
    tc_gemm_kernel<<<grid, 256, 65536>>>(kv_x, bfhi + 2 * 8192, bflo + 2 * 8192, vb, 0, 1.f);
    tc_gemm_kernel<<<grid, 256, 65536>>>(q_x,  bfhi + 3 * 8192, bflo + 3 * 8192, gb, 2, 1.f);

    attn_mma_kernel<<<dim3(NSEQ, NHEAD), 256>>>(qb, kb, vb, gb, tri, mbp, ob);

    tc_gemm_kernel<<<grid, 256, 65536>>>(ob, bfhi + 4 * 8192, bflo + 4 * 8192, out, 0, 1.f);
}

// round 15
// speedup vs baseline: 2.5831x; 1.0062x over previous
#include <cuda_runtime.h>
#include <cuda_bf16.h>
#include <math.h>
#include <stdint.h>

// Problem constants: B=1, N=256, Q=K=256, C=128, H=4, C_HID=32
#define NROW   65536
#define CDIM   128
#define NSEQ   256
#define NHEAD  4
#define LOG2E  1.4426950408889634f

// Scratch (allocation-free rule: __device__ globals)
__device__ float g_qbuf[(size_t)NROW * CDIM];
__device__ float g_kbuf[(size_t)NROW * CDIM];
__device__ float g_vbuf[(size_t)NROW * CDIM];
__device__ float g_gbuf[(size_t)NROW * CDIM];
__device__ float g_obuf[(size_t)NROW * CDIM];
// W in mma-B-fragment order, split bf16: [5 matrices][8192 u32]
__device__ uint32_t g_bfhi[5][8192];
__device__ uint32_t g_bflo[5][8192];

typedef unsigned long long ull;

// ---------------------------------------------------------------------------
// helpers
// ---------------------------------------------------------------------------
__device__ __forceinline__ uint32_t pack_bf2(float x0, float x1) {
    uint32_t r;
    asm("cvt.rn.bf16x2.f32 %0, %1, %2;" : "=r"(r) : "f"(x1), "f"(x0));
    return r;
}
__device__ __forceinline__ void split_bf2(float x0, float x1,
                                          uint32_t& hi, uint32_t& lo) {
    hi = pack_bf2(x0, x1);
    float h0 = __uint_as_float(hi << 16);
    float h1 = __uint_as_float(hi & 0xffff0000u);
    lo = pack_bf2(x0 - h0, x1 - h1);
}
__device__ __forceinline__ void mma_bf16(float c[4],
    uint32_t a0, uint32_t a1, uint32_t a2, uint32_t a3,
    uint32_t b0, uint32_t b1)
{
    asm("mma.sync.aligned.m16n8k16.row.col.f32.bf16.bf16.f32 "
        "{%0,%1,%2,%3}, {%4,%5,%6,%7}, {%8,%9}, {%0,%1,%2,%3};"
        : "+f"(c[0]), "+f"(c[1]), "+f"(c[2]), "+f"(c[3])
        : "r"(a0), "r"(a1), "r"(a2), "r"(a3), "r"(b0), "r"(b1));
}
__device__ __forceinline__ float ex2f(float x) {
    float r; asm("ex2.approx.f32 %0, %1;" : "=f"(r) : "f"(x)); return r;
}
__device__ __forceinline__ uint32_t smem_u32(const void* p) {
    uint32_t a;
    asm("{ .reg .u64 t; cvta.to.shared.u64 t, %1; cvt.u32.u64 %0, t; }"
        : "=r"(a) : "l"(p));
    return a;
}
__device__ __forceinline__ void cp16(uint32_t dst, const void* src) {
    asm volatile("cp.async.cg.shared.global [%0], [%1], 16;"
                 :: "r"(dst), "l"(src) : "memory");
}

// ---------------------------------------------------------------------------
// Weight prep: W[k][n] (5 matrices) -> split-bf16 B fragments in gmem.
// ---------------------------------------------------------------------------
__global__ void wprep_kernel(const float* __restrict__ W0,
                             const float* __restrict__ W1,
                             const float* __restrict__ W2,
                             const float* __restrict__ W3,
                             const float* __restrict__ W4)
{
    const float* Wm[5] = {W0, W1, W2, W3, W4};
    const int mat = blockIdx.y;
    const float* W = Wm[mat];
    int i = blockIdx.x * 256 + threadIdx.x;      // 0..4095
    int lane = i & 31, t = i >> 5;
    int ntile = t & 15, kstep = t >> 4;
    int n  = ntile * 8 + (lane >> 2);
    int kb = kstep * 16 + (lane & 3) * 2;

    float w00 = W[kb * 128 + n];
    float w01 = W[(kb + 1) * 128 + n];
    float w10 = W[(kb + 8) * 128 + n];
    float w11 = W[(kb + 9) * 128 + n];

    uint32_t h0, l0, h1, l1;
    split_bf2(w00, w01, h0, l0);
    split_bf2(w10, w11, h1, l1);
    g_bfhi[mat][i * 2]     = h0;
    g_bfhi[mat][i * 2 + 1] = h1;
    g_bflo[mat][i * 2]     = l0;
    g_bflo[mat][i * 2 + 1] = l1;
}

// ---------------------------------------------------------------------------
// HMMA GEMM: Y = epi(X @ W), split-bf16 3-term. B in 64KB smem; dist-1
// prefetch over n-tiles AND dist-1 X-register prefetch over ks.
// ---------------------------------------------------------------------------
__global__ void __launch_bounds__(256, 2) tc_gemm_kernel(
    const float* __restrict__ X,
    const uint32_t* __restrict__ Bhi,
    const uint32_t* __restrict__ Blo,
    float* __restrict__ Y, int op, float alpha)
{
    extern __shared__ ull sB[];                  // [2][4096]: hi then lo

    const int tid = threadIdx.x;
    const int w   = tid >> 5;
    const int l   = tid & 31;
    const int r0  = blockIdx.x * 128 + w * 16 + (l >> 2);
    const int r1  = r0 + 8;
    const int cq  = (l & 3) * 2;

    {
        const uint4* bh4 = (const uint4*)Bhi;
        const uint4* bl4 = (const uint4*)Blo;
        uint4* s4h = (uint4*)sB;
        uint4* s4l = (uint4*)(sB + 4096);
#pragma unroll
        for (int i = 0; i < 8; i++) {
            s4h[tid + 256 * i] = bh4[tid + 256 * i];
            s4l[tid + 256 * i] = bl4[tid + 256 * i];
        }
    }

    float acc[16][4];
#pragma unroll
    for (int nt = 0; nt < 16; nt++)
#pragma unroll
        for (int j = 0; j < 4; j++) acc[nt][j] = 0.f;

    const float* x0 = X + (size_t)r0 * 128;
    const float* x1 = X + (size_t)r1 * 128;

    __syncthreads();

    float2 xa = *(const float2*)(x0 + cq);
    float2 xb = *(const float2*)(x1 + cq);
    float2 xc = *(const float2*)(x0 + cq + 8);
    float2 xd = *(const float2*)(x1 + cq + 8);

#pragma unroll
    for (int ks = 0; ks < 8; ks++) {
        float2 na, nb, nc, nd;
        if (ks < 7) {
            const int cbn = (ks + 1) * 16 + cq;
            na = *(const float2*)(x0 + cbn);
            nb = *(const float2*)(x1 + cbn);
            nc = *(const float2*)(x0 + cbn + 8);
            nd = *(const float2*)(x1 + cbn + 8);
        }
        uint32_t ah0, al0, ah1, al1, ah2, al2, ah3, al3;
        split_bf2(xa.x, xa.y, ah0, al0);
        split_bf2(xb.x, xb.y, ah1, al1);
        split_bf2(xc.x, xc.y, ah2, al2);
        split_bf2(xd.x, xd.y, ah3, al3);

        const ull* bh = sB + ks * 512 + l;
        const ull* bl = bh + 4096;

        ull hcur = bh[0], lcur = bl[0];
#pragma unroll
        for (int nt = 0; nt < 16; nt++) {
            ull hnxt = 0, lnxt = 0;
            if (nt < 15) {
                hnxt = bh[(nt + 1) * 32];
                lnxt = bl[(nt + 1) * 32];
            }
            uint32_t bh0 = (uint32_t)hcur, bh1 = (uint32_t)(hcur >> 32);
            uint32_t bl0 = (uint32_t)lcur, bl1 = (uint32_t)(lcur >> 32);
            mma_bf16(acc[nt], ah0, ah1, ah2, ah3, bh0, bh1);
            mma_bf16(acc[nt], al0, al1, al2, al3, bh0, bh1);
            mma_bf16(acc[nt], ah0, ah1, ah2, ah3, bl0, bl1);
            hcur = hnxt; lcur = lnxt;
        }
        if (ks < 7) { xa = na; xb = nb; xc = nc; xd = nd; }
    }

    float* y0 = Y + (size_t)r0 * 128 + cq;
    float* y1 = Y + (size_t)r1 * 128 + cq;
#pragma unroll
    for (int nt = 0; nt < 16; nt++) {
        float2 p0 = make_float2(acc[nt][0], acc[nt][1]);
        float2 p1 = make_float2(acc[nt][2], acc[nt][3]);
        if (op == 1) {
            p0.x *= alpha; p0.y *= alpha; p1.x *= alpha; p1.y *= alpha;
        } else if (op == 2) {
            p0.x = 1.f / (1.f + __expf(-p0.x));
            p0.y = 1.f / (1.f + __expf(-p0.y));
            p1.x = 1.f / (1.f + __expf(-p1.x));
            p1.y = 1.f / (1.f + __expf(-p1.y));
        }
        *(float2*)(y0 + nt * 8) = p0;
        *(float2*)(y1 + nt * 8) = p1;
    }
}

// ---------------------------------------------------------------------------
// HMMA flash attention, R14 + cp.async raw K/V double buffer + log2-domain
// softmax (ex2). Dynamic smem layout (u32 units):
//   s_khi 1280 | s_klo 1280 | s_vhi 1152 | s_vlo 1152 | s_mb 256 |
//   s_raw 9216 (2 bufs x [K 2304 | V 2304], rows padded to 36 floats)
// total 14336 u32 = 57344 B.
// ---------------------------------------------------------------------------
#define ATTN_SMEM 57344

__global__ void __launch_bounds__(256) attn_mma_kernel(
    const float* __restrict__ qb, const float* __restrict__ kb,
    const float* __restrict__ vb, const float* __restrict__ gb,
    const float* __restrict__ tri, const float* __restrict__ mb,
    float* __restrict__ ob)
{
    extern __shared__ uint32_t s_mem[];
    uint32_t* s_khi = s_mem;             // [64*20]
    uint32_t* s_klo = s_khi + 1280;
    uint32_t* s_vhi = s_klo + 1280;      // [32*36]
    uint32_t* s_vlo = s_vhi + 1152;
    float*    s_mb  = (float*)(s_vlo + 1152);       // [256]
    float*    s_raw = (float*)(s_mb + 256);         // [2][2][64*36]

    const int n   = blockIdx.x;
    const int h   = blockIdx.y;
    const int tid = threadIdx.x;
    const int w   = tid >> 5;
    const int l   = tid & 31;
    const int lq  = l >> 2;
    const int lc  = l & 3;
    const int wb  = w * 32;

    s_mb[tid] = mb[(size_t)n * 256 + tid] * LOG2E;

    // ---- Q fragments (split bf16) ----
    uint32_t qh[2][2][4], ql[2][2][4];
#pragma unroll
    for (int mt = 0; mt < 2; mt++) {
        const int rA = wb + mt * 16 + lq;
        const int rB = rA + 8;
        const float* qA = qb + ((size_t)(n * 256 + rA)) * 128 + h * 32;
        const float* qB = qb + ((size_t)(n * 256 + rB)) * 128 + h * 32;
#pragma unroll
        for (int ks = 0; ks < 2; ks++) {
            const int k0 = ks * 16 + lc * 2;
            float2 x0 = *(const float2*)(qA + k0);
            float2 x1 = *(const float2*)(qB + k0);
            float2 x2 = *(const float2*)(qA + k0 + 8);
            float2 x3 = *(const float2*)(qB + k0 + 8);
            split_bf2(x0.x, x0.y, qh[mt][ks][0], ql[mt][ks][0]);
            split_bf2(x1.x, x1.y, qh[mt][ks][1], ql[mt][ks][1]);
            split_bf2(x2.x, x2.y, qh[mt][ks][2], ql[mt][ks][2]);
            split_bf2(x3.x, x3.y, qh[mt][ks][3], ql[mt][ks][3]);
        }
    }

    float oa[2][4][4];
#pragma unroll
    for (int mt = 0; mt < 2; mt++)
#pragma unroll
        for (int nt = 0; nt < 4; nt++)
#pragma unroll
            for (int j = 0; j < 4; j++) oa[mt][nt][j] = 0.f;
    float mrun[2][2] = {{-INFINITY, -INFINITY}, {-INFINITY, -INFINITY}};
    float lrun[2][2] = {{0.f, 0.f}, {0.f, 0.f}};

    // ---- cp.async prefetch of raw K/V tile (rows padded to 36 floats) ----
    const int prow = tid >> 3, pch = tid & 7;       // 2 chunks per thread per array
#define PREFETCH_KV(JT, BUF) do { \
    float* rawk = s_raw + (BUF) * 4608; \
    float* rawv = rawk + 2304; \
    _Pragma("unroll") \
    for (int it = 0; it < 2; it++) { \
        int row = prow + 32 * it; \
        const float* srck = kb + ((size_t)(n * 256 + (JT) + row)) * 128 + h * 32 + pch * 4; \
        const float* srcv = vb + ((size_t)(n * 256 + (JT) + row)) * 128 + h * 32 + pch * 4; \
        cp16(smem_u32(rawk + row * 36 + pch * 4), srck); \
        cp16(smem_u32(rawv + row * 36 + pch * 4), srcv); \
    } \
    asm volatile("cp.async.commit_group;" ::: "memory"); \
} while (0)

    PREFETCH_KV(0, 0);

    for (int t = 0; t < 4; t++) {
        const int jt = t * 64;
        if (t < 3) PREFETCH_KV(jt + 64, (t + 1) & 1);
        if (t < 3) asm volatile("cp.async.wait_group 1;" ::: "memory");
        else       asm volatile("cp.async.wait_group 0;" ::: "memory");
        __syncthreads();   // raw[t&1] visible to all; split arrays free

        // ---- split raw -> bf16-split smem arrays ----
        {
            const float* rawk = s_raw + (t & 1) * 4608;
            const float* rawv = rawk + 2304;
            const int key = tid >> 2, g = tid & 3;
#pragma unroll
            for (int it = 0; it < 2; it++) {
                const int g2 = g + 4 * it;
                float4 kv = *(const float4*)(rawk + key * 36 + 4 * g2);
                uint32_t h0, l0, h1, l1;
                split_bf2(kv.x, kv.y, h0, l0);
                split_bf2(kv.z, kv.w, h1, l1);
                s_khi[key * 20 + 2 * g2]     = h0;
                s_khi[key * 20 + 2 * g2 + 1] = h1;
                s_klo[key * 20 + 2 * g2]     = l0;
                s_klo[key * 20 + 2 * g2 + 1] = l1;
            }
#pragma unroll
            for (int it = 0; it < 2; it++) {
                const int idx = tid + 256 * it;
                const int kp = idx >> 4, c = (idx & 15) * 2;
                float2 a = *(const float2*)(rawv + (2 * kp) * 36 + c);
                float2 b = *(const float2*)(rawv + (2 * kp + 1) * 36 + c);
                uint32_t h0, l0, h1, l1;
                split_bf2(a.x, b.x, h0, l0);
                split_bf2(a.y, b.y, h1, l1);
                s_vhi[c * 36 + kp]       = h0;
                s_vlo[c * 36 + kp]       = l0;
                s_vhi[(c + 1) * 36 + kp] = h1;
                s_vlo[(c + 1) * 36 + kp] = l1;
            }
        }
        __syncthreads();

#pragma unroll
        for (int mt = 0; mt < 2; mt++) {
            const int rA = wb + mt * 16 + lq;
            const int rB = rA + 8;
            const float* tA = tri + ((size_t)(h * 256 + rA)) * 256 + jt;
            const float* tB = tri + ((size_t)(h * 256 + rB)) * 256 + jt;

            // ---- S acc preloaded with (tri*log2e + mb*log2e) ----
            float sc[8][4];
#pragma unroll
            for (int nt = 0; nt < 8; nt++) {
                const int col = nt * 8 + lc * 2;
                float2 bA = *(const float2*)(tA + col);
                float2 bB = *(const float2*)(tB + col);
                float2 mv = *(const float2*)&s_mb[jt + col];
                sc[nt][0] = fmaf(bA.x, LOG2E, mv.x);
                sc[nt][1] = fmaf(bA.y, LOG2E, mv.y);
                sc[nt][2] = fmaf(bB.x, LOG2E, mv.x);
                sc[nt][3] = fmaf(bB.y, LOG2E, mv.y);
            }
            // ---- S += Q K^T (Q pre-scaled by log2e) ----
#pragma unroll
            for (int nt = 0; nt < 8; nt++) {
                const uint32_t* kh = &s_khi[(nt * 8 + lq) * 20];
                const uint32_t* kl = &s_klo[(nt * 8 + lq) * 20];
#pragma unroll
                for (int ks = 0; ks < 2; ks++) {
                    uint32_t b0h = kh[ks * 8 + lc], b1h = kh[ks * 8 + 4 + lc];
                    uint32_t b0l = kl[ks * 8 + lc], b1l = kl[ks * 8 + 4 + lc];
                    mma_bf16(sc[nt], qh[mt][ks][0], qh[mt][ks][1],
                             qh[mt][ks][2], qh[mt][ks][3], b0h, b1h);
                    mma_bf16(sc[nt], ql[mt][ks][0], ql[mt][ks][1],
                             ql[mt][ks][2], ql[mt][ks][3], b0h, b1h);
                    mma_bf16(sc[nt], qh[mt][ks][0], qh[mt][ks][1],
                             qh[mt][ks][2], qh[mt][ks][3], b0l, b1l);
                }
            }
            // ---- online softmax (log2 domain) ----
            float mxA = sc[0][0], mxB = sc[0][2];
#pragma unroll
            for (int nt = 0; nt < 8; nt++) {
                mxA = fmaxf(mxA, fmaxf(sc[nt][0], sc[nt][1]));
                mxB = fmaxf(mxB, fmaxf(sc[nt][2], sc[nt][3]));
            }
            mxA = fmaxf(mxA, __shfl_xor_sync(0xffffffffu, mxA, 1));
            mxA = fmaxf(mxA, __shfl_xor_sync(0xffffffffu, mxA, 2));
            mxB = fmaxf(mxB, __shfl_xor_sync(0xffffffffu, mxB, 1));
            mxB = fmaxf(mxB, __shfl_xor_sync(0xffffffffu, mxB, 2));
            float mnA = fmaxf(mrun[mt][0], mxA);
            float mnB = fmaxf(mrun[mt][1], mxB);
            float corrA = ex2f(mrun[mt][0] - mnA);
            float corrB = ex2f(mrun[mt][1] - mnB);
            mrun[mt][0] = mnA; mrun[mt][1] = mnB;
            float sumA = 0.f, sumB = 0.f;
#pragma unroll
            for (int nt = 0; nt < 8; nt++) {
                sc[nt][0] = ex2f(sc[nt][0] - mnA);
                sc[nt][1] = ex2f(sc[nt][1] - mnA);
                sc[nt][2] = ex2f(sc[nt][2] - mnB);
                sc[nt][3] = ex2f(sc[nt][3] - mnB);
                sumA += sc[nt][0] + sc[nt][1];
                sumB += sc[nt][2] + sc[nt][3];
            }
            lrun[mt][0] = lrun[mt][0] * corrA + sumA;
            lrun[mt][1] = lrun[mt][1] * corrB + sumB;
#pragma unroll
            for (int nt = 0; nt < 4; nt++) {
                oa[mt][nt][0] *= corrA; oa[mt][nt][1] *= corrA;
                oa[mt][nt][2] *= corrB; oa[mt][nt][3] *= corrB;
            }
            // ---- O += P V ----
#pragma unroll
            for (int ks = 0; ks < 4; ks++) {
                uint32_t ph[4], pl[4];
                split_bf2(sc[2 * ks][0],     sc[2 * ks][1],     ph[0], pl[0]);
                split_bf2(sc[2 * ks][2],     sc[2 * ks][3],     ph[1], pl[1]);
                split_bf2(sc[2 * ks + 1][0], sc[2 * ks + 1][1], ph[2], pl[2]);
                split_bf2(sc[2 * ks + 1][2], sc[2 * ks + 1][3], ph[3], pl[3]);
#pragma unroll
                for (int nt = 0; nt < 4; nt++) {
                    const uint32_t* vh = &s_vhi[(nt * 8 + lq) * 36];
                    const uint32_t* vl = &s_vlo[(nt * 8 + lq) * 36];
                    uint32_t b0h = vh[ks * 8 + lc], b1h = vh[ks * 8 + 4 + lc];
                    uint32_t b0l = vl[ks * 8 + lc], b1l = vl[ks * 8 + 4 + lc];
                    mma_bf16(oa[mt][nt], ph[0], ph[1], ph[2], ph[3], b0h, b1h);
                    mma_bf16(oa[mt][nt], pl[0], pl[1], pl[2], pl[3], b0h, b1h);
                    mma_bf16(oa[mt][nt], ph[0], ph[1], ph[2], ph[3], b0l, b1l);
                }
            }
        }
    }

    // ---- epilogue: normalize, gate, store ----
#pragma unroll
    for (int mt = 0; mt < 2; mt++) {
        float lA = lrun[mt][0], lB = lrun[mt][1];
        lA += __shfl_xor_sync(0xffffffffu, lA, 1);
        lA += __shfl_xor_sync(0xffffffffu, lA, 2);
        lB += __shfl_xor_sync(0xffffffffu, lB, 1);
        lB += __shfl_xor_sync(0xffffffffu, lB, 2);
        const float invA = 1.f / lA, invB = 1.f / lB;
        const int rA = wb + mt * 16 + lq;
        const int rB = rA + 8;
        const float* gA = gb + ((size_t)(n * 256 + rA)) * 128 + h * 32;
        const float* gB = gb + ((size_t)(n * 256 + rB)) * 128 + h * 32;
        float* oA = ob + ((size_t)(n * 256 + rA)) * 128 + h * 32;
        float* oB = ob + ((size_t)(n * 256 + rB)) * 128 + h * 32;
#pragma unroll
        for (int nt = 0; nt < 4; nt++) {
            const int col = nt * 8 + lc * 2;
            float2 ga = *(const float2*)(gA + col);
            float2 gc = *(const float2*)(gB + col);
            float2 o0, o1;
            o0.x = oa[mt][nt][0] * invA * ga.x;
            o0.y = oa[mt][nt][1] * invA * ga.y;
            o1.x = oa[mt][nt][2] * invB * gc.x;
            o1.y = oa[mt][nt][3] * invB * gc.y;
            *(float2*)(oA + col) = o0;
            *(float2*)(oB + col) = o1;
        }
    }
}

// ---------------------------------------------------------------------------
// Launch. Inputs: q_x, kv_x, tri_bias, mask_bias, mask(unused), Wq,Wk,Wv,Wg,Wo
// ---------------------------------------------------------------------------
extern "C" void kernel_launch(void* const* d_in, const int* in_sizes, int n_in,
                              void* d_out, int out_size)
{
    const float* q_x  = (const float*)d_in[0];
    const float* kv_x = (const float*)d_in[1];
    const float* tri  = (const float*)d_in[2];
    const float* mbp  = (const float*)d_in[3];
    float* out = (float*)d_out;

    float *qb, *kb, *vb, *gb, *ob;
    cudaGetSymbolAddress((void**)&qb, g_qbuf);
    cudaGetSymbolAddress((void**)&kb, g_kbuf);
    cudaGetSymbolAddress((void**)&vb, g_vbuf);
    cudaGetSymbolAddress((void**)&gb, g_gbuf);
    cudaGetSymbolAddress((void**)&ob, g_obuf);
    uint32_t *bfhi, *bflo;
    cudaGetSymbolAddress((void**)&bfhi, g_bfhi);
    cudaGetSymbolAddress((void**)&bflo, g_bflo);

    static int smem_set = -1;
    if (smem_set < 0) {
        cudaFuncSetAttribute(tc_gemm_kernel,
                             cudaFuncAttributeMaxDynamicSharedMemorySize, 65536);
        cudaFuncSetAttribute(attn_mma_kernel,
                             cudaFuncAttributeMaxDynamicSharedMemorySize, ATTN_SMEM);
        smem_set = 1;
    }

    wprep_kernel<<<dim3(16, 5), 256>>>(
        (const float*)d_in[5], (const float*)d_in[6], (const float*)d_in[7],
        (const float*)d_in[8], (const float*)d_in[9]);

    const int grid = NROW / 128;  // 512
    const float qalpha = 0.17677669529663687f * LOG2E;  // 1/sqrt(32) * log2e

    tc_gemm_kernel<<<grid, 256, 65536>>>(q_x,  bfhi + 0 * 8192, bflo + 0 * 8192, qb, 1, qalpha);
    tc_gemm_kernel<<<grid, 256, 65536>>>(kv_x, bfhi + 1 * 8192, bflo + 1 * 8192, kb, 0, 1.f);
    tc_gemm_kernel<<<grid, 256, 65536>>>(kv_x, bfhi + 2 * 8192, bflo + 2 * 8192, vb, 0, 1.f);
    tc_gemm_kernel<<<grid, 256, 65536>>>(q_x,  bfhi + 3 * 8192, bflo + 3 * 8192, gb, 2, 1.f);

    attn_mma_kernel<<<dim3(NSEQ, NHEAD), 256, ATTN_SMEM>>>(qb, kb, vb, gb, tri, mbp, ob);

    tc_gemm_kernel<<<grid, 256, 65536>>>(ob, bfhi + 4 * 8192, bflo + 4 * 8192, out, 0, 1.f);
}